// round 1
// baseline (speedup 1.0000x reference)
#include <cuda_runtime.h>
#include <cstdint>

#define HDIM 128
#define TSEQ 512
#define BATCH 128
#define GB 4          // batches per cluster
#define RSTRIDE 132   // padded row stride (floats) -> conflict-free float4 LDS
#define NROW 128      // gate rows per CTA slice (4 gates x 32 units)

// scratch (device globals: allocation-free rule)
__device__ float g_h2[(size_t)TSEQ * BATCH * HDIM];   // [t][b][h]
__device__ float g_dold[TSEQ * BATCH];                // h2 . wt_old
__device__ float g_dh[TSEQ * BATCH];                  // h2 . wt_h

__device__ __forceinline__ float sigm(float x) {
    return __fdividef(1.f, 1.f + __expf(-x));
}
__device__ __forceinline__ float tanh_fast(float x) {
    x = fminf(fmaxf(x, -15.f), 15.f);
    float e = __expf(2.f * x);
    return __fdividef(e - 1.f, e + 1.f);
}

__device__ __forceinline__ void st_cluster_f32(float* p, int rank, float v) {
    uint32_t la = (uint32_t)__cvta_generic_to_shared(p);
    uint32_t ra;
    asm volatile("mapa.shared::cluster.u32 %0, %1, %2;" : "=r"(ra) : "r"(la), "r"(rank));
    asm volatile("st.shared::cluster.f32 [%0], %1;" :: "r"(ra), "f"(v) : "memory");
}

__device__ __forceinline__ void cluster_sync_() {
    asm volatile("barrier.cluster.arrive.aligned;" ::: "memory");
    asm volatile("barrier.cluster.wait.aligned;" ::: "memory");
}

// ---------------------------------------------------------------------------
// Phase 1: the sequential 2-layer LSTM recurrence.
// Grid = 128 CTAs = 32 clusters x 4. Cluster g handles batches 4g..4g+3.
// CTA rank r owns hidden units [32r, 32r+32): for each of the 3 weight
// matrices it keeps the 128 corresponding gate rows in SMEM (fp32).
// Per step: gates1 -> cell1 -> DSMEM-broadcast h1,c1 -> sync ->
//           gates2 -> cell2 -> DSMEM-broadcast h2 + store h2 to global -> sync.
// Activation buffers double-buffered (parity p) so 2 syncs/step suffice.
// ---------------------------------------------------------------------------
__global__ void __launch_bounds__(512, 1) __cluster_dims__(4, 1, 1)
lstm_seq_kernel(const float* __restrict__ x,
                const float* __restrict__ Wih1, const float* __restrict__ Whh1,
                const float* __restrict__ bih1, const float* __restrict__ bhh1,
                const float* __restrict__ Wih2, const float* __restrict__ Whh2,
                const float* __restrict__ bih2, const float* __restrict__ bhh2)
{
    extern __shared__ float dyn[];
    float* sW1  = dyn;                      // [128][132]
    float* sW2i = dyn + NROW * RSTRIDE;     // [128][132]
    float* sW2h = dyn + 2 * NROW * RSTRIDE; // [128][132]

    __shared__ float h1buf[2][GB][RSTRIDE];
    __shared__ float c1buf[2][GB][RSTRIDE];
    __shared__ float h2buf[2][GB][RSTRIDE];
    __shared__ float xs[GB][TSEQ];
    __shared__ float gbuf[512];             // [row*4 + batch]
    __shared__ float bias1s[NROW], bias2s[NROW], wih1s[NROW];

    const int tid  = threadIdx.x;
    const int rank = blockIdx.x & 3;
    const int bg0  = (blockIdx.x >> 2) * GB;

    // ---- load weights slice: local row j = gate*32 + u  <->  global row gate*128 + rank*32 + u
    for (int idx = tid; idx < NROW * 32; idx += 512) {
        int j = idx >> 5, k4 = idx & 31;
        int gr = (j >> 5) * 128 + rank * 32 + (j & 31);
        ((float4*)(sW1  + j * RSTRIDE))[k4] = ((const float4*)(Whh1 + (size_t)gr * 128))[k4];
        ((float4*)(sW2i + j * RSTRIDE))[k4] = ((const float4*)(Wih2 + (size_t)gr * 128))[k4];
        ((float4*)(sW2h + j * RSTRIDE))[k4] = ((const float4*)(Whh2 + (size_t)gr * 128))[k4];
    }
    if (tid < NROW) {
        int gr = (tid >> 5) * 128 + rank * 32 + (tid & 31);
        bias1s[tid] = bih1[gr] + bhh1[gr];
        bias2s[tid] = bih2[gr] + bhh2[gr];
        wih1s[tid]  = Wih1[gr];
    }
    for (int idx = tid; idx < GB * TSEQ; idx += 512) {
        int b = idx >> 9, tt = idx & (TSEQ - 1);
        xs[b][tt] = x[(size_t)(bg0 + b) * TSEQ + tt];
    }
    for (int idx = tid; idx < 2 * GB * RSTRIDE; idx += 512) {
        ((float*)h1buf)[idx] = 0.f;
        ((float*)c1buf)[idx] = 0.f;
        ((float*)h2buf)[idx] = 0.f;
    }
    __syncthreads();
    cluster_sync_();   // peers must not DSMEM-write our buffers before init completes

    const int j    = tid >> 2;   // matvec row 0..127 (warp = 8 rows x 4 batches)
    const int bb   = tid & 3;    // matvec batch
    const int cu   = tid & 31;   // cell: unit within slice (tid<128)
    const int cb   = tid >> 5;   // cell: batch (tid<128)
    const int slot = rank * 32 + cu;

    float c1 = 0.f, c2 = 0.f;    // cell state, valid for tid<128
    int p = 0;

    for (int t = 0; t < TSEQ; t++) {
        // ---- layer-1 gates: gbuf[j,b] = b1[j] + x*wih1[j] + Whh1_slice[j,:].h1
        {
            const float4* wr = (const float4*)(sW1 + j * RSTRIDE);
            const float4* hv = (const float4*)h1buf[p][bb];
            float4 s; s.x = s.y = s.z = s.w = 0.f;
            #pragma unroll
            for (int k = 0; k < 32; k++) {
                float4 w = wr[k], h = hv[k];
                s.x += w.x * h.x; s.y += w.y * h.y;
                s.z += w.z * h.z; s.w += w.w * h.w;
            }
            gbuf[tid] = bias1s[j] + xs[bb][t] * wih1s[j] + (s.x + s.y) + (s.z + s.w);
        }
        __syncthreads();
        // ---- cell 1 + broadcast h1,c1 slice to all 4 CTAs (buffer parity p^1)
        if (tid < 128) {
            float gi = gbuf[(cu)      * 4 + cb];
            float gf = gbuf[(32 + cu) * 4 + cb];
            float gg = gbuf[(64 + cu) * 4 + cb];
            float go = gbuf[(96 + cu) * 4 + cb];
            c1 = sigm(gf) * c1 + sigm(gi) * tanh_fast(gg);
            float h1v = sigm(go) * tanh_fast(c1);
            int pn = p ^ 1;
            #pragma unroll
            for (int r = 0; r < 4; r++) {
                st_cluster_f32(&h1buf[pn][cb][slot], r, h1v);
                st_cluster_f32(&c1buf[pn][cb][slot], r, c1);
            }
        }
        cluster_sync_();
        // ---- layer-2 gates: input is c1 (fresh), recurrent h2 (parity p)
        {
            const float4* wi = (const float4*)(sW2i + j * RSTRIDE);
            const float4* wh = (const float4*)(sW2h + j * RSTRIDE);
            const float4* cv = (const float4*)c1buf[p ^ 1][bb];
            const float4* hv = (const float4*)h2buf[p][bb];
            float4 s; s.x = s.y = s.z = s.w = 0.f;
            #pragma unroll
            for (int k = 0; k < 32; k++) {
                float4 a = wi[k], cc = cv[k];
                s.x += a.x * cc.x; s.y += a.y * cc.y;
                s.z += a.z * cc.z; s.w += a.w * cc.w;
                float4 bqw = wh[k], hh = hv[k];
                s.x += bqw.x * hh.x; s.y += bqw.y * hh.y;
                s.z += bqw.z * hh.z; s.w += bqw.w * hh.w;
            }
            gbuf[tid] = bias2s[j] + (s.x + s.y) + (s.z + s.w);
        }
        __syncthreads();
        // ---- cell 2 + broadcast h2 + store to global
        if (tid < 128) {
            float gi = gbuf[(cu)      * 4 + cb];
            float gf = gbuf[(32 + cu) * 4 + cb];
            float gg = gbuf[(64 + cu) * 4 + cb];
            float go = gbuf[(96 + cu) * 4 + cb];
            c2 = sigm(gf) * c2 + sigm(gi) * tanh_fast(gg);
            float h2v = sigm(go) * tanh_fast(c2);
            int pn = p ^ 1;
            #pragma unroll
            for (int r = 0; r < 4; r++)
                st_cluster_f32(&h2buf[pn][cb][slot], r, h2v);
            g_h2[(size_t)t * (BATCH * HDIM) + (size_t)(bg0 + cb) * HDIM + slot] = h2v;
        }
        cluster_sync_();
        p ^= 1;
    }
}

// ---------------------------------------------------------------------------
// Phase 2a: d_old[t,b] = h2[t,b].wt_old ; d_h[t,b] = h2[t,b].wt_h
// One warp per (t,b) pair.
// ---------------------------------------------------------------------------
__global__ void dots_kernel(const float* __restrict__ w_t)
{
    int gid  = blockIdx.x * blockDim.x + threadIdx.x;
    int gw   = gid >> 5;
    int lane = gid & 31;
    if (gw >= TSEQ * BATCH) return;
    float4 h = *(const float4*)(g_h2 + (size_t)gw * HDIM + lane * 4);
    float4 a = *(const float4*)(w_t + lane * 4);          // wt_h  = w_t[0:128]
    float4 o = *(const float4*)(w_t + HDIM + lane * 4);   // wt_old= w_t[128:256]
    float dh   = h.x * a.x + h.y * a.y + h.z * a.z + h.w * a.w;
    float dold = h.x * o.x + h.y * o.y + h.z * o.z + h.w * o.w;
    #pragma unroll
    for (int off = 16; off; off >>= 1) {
        dh   += __shfl_down_sync(0xffffffffu, dh, off);
        dold += __shfl_down_sync(0xffffffffu, dold, off);
    }
    if (lane == 0) { g_dh[gw] = dh; g_dold[gw] = dold; }
}

// ---------------------------------------------------------------------------
// Phase 2b: per timestep t: global softmax over (slot,batch), attention gather,
// pre = h2[t] + attn, then out[b,t,:] = pre @ fcW^T + fcb. One CTA per t.
// ---------------------------------------------------------------------------
__global__ void __launch_bounds__(256, 1)
attn_fc_kernel(const float* __restrict__ fcW, const float* __restrict__ fcb,
               float* __restrict__ out)
{
    extern __shared__ float sm[];
    float* sFcT = sm;                       // [128][132]: fcW^T as [h][c]
    float* sPre = sFcT + 128 * RSTRIDE;     // [128][132]: pre as [b][h]
    float* sE   = sPre + 128 * RSTRIDE;     // [33][128] unnormalized exp
    float* sHd  = sE + 33 * 128;            // [128] d_h[t, b]
    float* sFcb = sHd + 128;                // [128]
    float* sRed = sFcb + 128;               // [256]

    const int t    = blockIdx.x;
    const int tid  = threadIdx.x;
    const int lane = tid & 31;
    const int warp = tid >> 5;

    // fcW transpose into SMEM (global read coalesced over h)
    for (int idx = tid; idx < 128 * 128; idx += 256) {
        int c = idx >> 7, h = idx & 127;
        sFcT[h * RSTRIDE + c] = fcW[idx];
    }
    if (tid < 128) {
        sFcb[tid] = fcb[tid];
        sHd[tid]  = g_dh[t * BATCH + tid];
    }
    __syncthreads();

    // scores for valid slots s in [s_min, 32]; slot index -> h2 time idx = t-33+s
    const int s_min = (t < 32) ? (32 - t) : 0;
    const int nsc   = (33 - s_min) * 128;
    float lmax = -1e30f;
    for (int n = tid; n < nsc; n += 256) {
        int s = s_min + (n >> 7), b = n & 127;
        int idx = t - 33 + s;
        float sc = sHd[b] + (idx >= 0 ? g_dold[idx * BATCH + b] : 0.f);
        sE[s * 128 + b] = sc;
        lmax = fmaxf(lmax, sc);
    }
    sRed[tid] = lmax; __syncthreads();
    for (int off = 128; off; off >>= 1) {
        if (tid < off) sRed[tid] = fmaxf(sRed[tid], sRed[tid + off]);
        __syncthreads();
    }
    float mx = sRed[0];
    __syncthreads();
    float lsum = 0.f;
    for (int n = tid; n < nsc; n += 256) {
        int s = s_min + (n >> 7), b = n & 127;
        float e = __expf(sE[s * 128 + b] - mx);
        sE[s * 128 + b] = e;
        lsum += e;
    }
    sRed[tid] = lsum; __syncthreads();
    for (int off = 128; off; off >>= 1) {
        if (tid < off) sRed[tid] += sRed[tid + off];
        __syncthreads();
    }
    float inv = __fdividef(1.f, sRed[0]);
    __syncthreads();

    // attention gather + pre.  Warp owns batch b (lane covers h in float4 chunks).
    const int s_att = (t < 33) ? (33 - t) : 0;  // slots with a real (idx>=0) buffer entry
    for (int b = warp; b < 128; b += 8) {
        float4 acc; acc.x = acc.y = acc.z = acc.w = 0.f;
        for (int s = s_att; s < 33; s++) {
            float w  = sE[s * 128 + b];
            float4 v = *(const float4*)(g_h2 + (size_t)(t - 33 + s) * (BATCH * HDIM)
                                              + (size_t)b * HDIM + lane * 4);
            acc.x += w * v.x; acc.y += w * v.y; acc.z += w * v.z; acc.w += w * v.w;
        }
        float4 hc = *(const float4*)(g_h2 + (size_t)t * (BATCH * HDIM)
                                           + (size_t)b * HDIM + lane * 4);
        float4 pre;
        pre.x = hc.x + inv * acc.x; pre.y = hc.y + inv * acc.y;
        pre.z = hc.z + inv * acc.z; pre.w = hc.w + inv * acc.w;
        *(float4*)(sPre + b * RSTRIDE + lane * 4) = pre;
    }
    __syncthreads();

    // FC: out[b][t][c] = fcb[c] + sum_h pre[b][h] * fcW[c][h]
    // thread = (lane -> 4 c's) x (warp -> b quads), register-tiled 4b x 4c.
    const int c0 = lane * 4;
    float4 bias = *(const float4*)(sFcb + c0);
    for (int r = 0; r < 4; r++) {
        int b0 = (warp + 8 * r) * 4;
        float4 a0, a1, a2, a3;
        a0.x=a0.y=a0.z=a0.w=0.f; a1=a0; a2=a0; a3=a0;
        const float4* p0 = (const float4*)(sPre + (size_t)(b0 + 0) * RSTRIDE);
        const float4* p1 = (const float4*)(sPre + (size_t)(b0 + 1) * RSTRIDE);
        const float4* p2 = (const float4*)(sPre + (size_t)(b0 + 2) * RSTRIDE);
        const float4* p3 = (const float4*)(sPre + (size_t)(b0 + 3) * RSTRIDE);
        #pragma unroll
        for (int h4 = 0; h4 < 32; h4++) {
            float4 q0 = p0[h4], q1 = p1[h4], q2 = p2[h4], q3 = p3[h4];
            #pragma unroll
            for (int hh = 0; hh < 4; hh++) {
                float4 w = *(const float4*)(sFcT + (h4 * 4 + hh) * RSTRIDE + c0);
                float v0 = (&q0.x)[hh], v1 = (&q1.x)[hh], v2 = (&q2.x)[hh], v3 = (&q3.x)[hh];
                a0.x += v0 * w.x; a0.y += v0 * w.y; a0.z += v0 * w.z; a0.w += v0 * w.w;
                a1.x += v1 * w.x; a1.y += v1 * w.y; a1.z += v1 * w.z; a1.w += v1 * w.w;
                a2.x += v2 * w.x; a2.y += v2 * w.y; a2.z += v2 * w.z; a2.w += v2 * w.w;
                a3.x += v3 * w.x; a3.y += v3 * w.y; a3.z += v3 * w.z; a3.w += v3 * w.w;
            }
        }
        a0.x += bias.x; a0.y += bias.y; a0.z += bias.z; a0.w += bias.w;
        a1.x += bias.x; a1.y += bias.y; a1.z += bias.z; a1.w += bias.w;
        a2.x += bias.x; a2.y += bias.y; a2.z += bias.z; a2.w += bias.w;
        a3.x += bias.x; a3.y += bias.y; a3.z += bias.z; a3.w += bias.w;
        size_t obase = (size_t)t * 128 + c0;
        *(float4*)(out + (size_t)(b0 + 0) * (TSEQ * 128) + obase) = a0;
        *(float4*)(out + (size_t)(b0 + 1) * (TSEQ * 128) + obase) = a1;
        *(float4*)(out + (size_t)(b0 + 2) * (TSEQ * 128) + obase) = a2;
        *(float4*)(out + (size_t)(b0 + 3) * (TSEQ * 128) + obase) = a3;
    }
}

// ---------------------------------------------------------------------------
extern "C" void kernel_launch(void* const* d_in, const int* in_sizes, int n_in,
                              void* d_out, int out_size)
{
    const float* x    = (const float*)d_in[0];
    const float* Wih1 = (const float*)d_in[1];
    const float* Whh1 = (const float*)d_in[2];
    const float* bih1 = (const float*)d_in[3];
    const float* bhh1 = (const float*)d_in[4];
    const float* Wih2 = (const float*)d_in[5];
    const float* Whh2 = (const float*)d_in[6];
    const float* bih2 = (const float*)d_in[7];
    const float* bhh2 = (const float*)d_in[8];
    const float* w_t  = (const float*)d_in[9];
    const float* fcW  = (const float*)d_in[10];
    const float* fcb  = (const float*)d_in[11];
    float* out = (float*)d_out;

    const int smem1 = 3 * NROW * RSTRIDE * (int)sizeof(float);                 // 202752
    const int smem3 = (2 * 128 * RSTRIDE + 33 * 128 + 128 + 128 + 256) * (int)sizeof(float); // 154112

    cudaFuncSetAttribute(lstm_seq_kernel, cudaFuncAttributeMaxDynamicSharedMemorySize, smem1);
    cudaFuncSetAttribute(attn_fc_kernel,  cudaFuncAttributeMaxDynamicSharedMemorySize, smem3);

    lstm_seq_kernel<<<128, 512, smem1>>>(x, Wih1, Whh1, bih1, bhh1,
                                         Wih2, Whh2, bih2, bhh2);
    dots_kernel<<<(TSEQ * BATCH * 32) / 256, 256>>>(w_t);
    attn_fc_kernel<<<TSEQ, 256, smem3>>>(fcW, fcb, out);
}